// round 11
// baseline (speedup 1.0000x reference)
#include <cuda_runtime.h>
#include <math.h>

#define DIM   768
#define D3    2304
#define BATCH 8
#define SLEN  256
#define TLEN  128
#define VOC   50257
#define NHEAD 12
#define HDIM  64
#define NBLK  96

typedef unsigned long long u64;

// ---------------- scratch (device globals; no allocation) ----------------
__device__ float g_buf[17301504];          // ~66 MB
__device__ float g_h[2][BATCH * DIM];      // GRU hidden ping-pong
__device__ float g_henc[BATCH * DIM];
__device__ unsigned long long g_best[1024];
__device__ double g_part[512];
__device__ unsigned g_cnt = 0;
__device__ unsigned g_gen = 0;

// g_buf offsets (floats)
#define OFF_SRC_E  0u
#define OFF_DST_E  1572864u
#define OFF_GI     2359296u
#define OFF_FINAL  7077888u
#define OFF_CAND   7864320u
#define OFF_Q      8650752u
#define OFF_KP     10223616u
#define OFF_VP     11010048u
#define OFF_AO     11796480u
#define OFF_COUT   13369344u
#define OFF_CAFT   14942208u
#define OFF_DSTOUT 16515072u

__device__ __forceinline__ float sigm(float x) { return 1.0f / (1.0f + expf(-x)); }

// ---- packed f32x2 helpers (Blackwell sm_103a) ----
__device__ __forceinline__ u64 packf2(float lo, float hi) {
    u64 r;
    asm("mov.b64 %0, {%1, %2};" : "=l"(r) : "f"(lo), "f"(hi));
    return r;
}
__device__ __forceinline__ void unpackf2(u64 v, float& lo, float& hi) {
    asm("mov.b64 {%0, %1}, %2;" : "=f"(lo), "=f"(hi) : "l"(v));
}
__device__ __forceinline__ void fma2(u64& d, u64 a, u64 b) {
    asm("fma.rn.f32x2 %0, %1, %2, %0;" : "+l"(d) : "l"(a), "l"(b));
}

// duplicated-B smem word offset: conflict-free skewed layout.
// off(n) = (n>>2)*10 + (n&3)*2  (each n occupies a (b,b) pair = 2 words)
__device__ __forceinline__ int boff(int n) {
    return (n >> 2) * 10 + (n & 3) * 2;
}

// Grid barrier for NBLK co-resident blocks (generation-based, monotone g_gen).
__device__ __forceinline__ void gbar(unsigned& gen) {
    __syncthreads();
    if (threadIdx.x == 0) {
        __threadfence();
        unsigned arr = atomicAdd(&g_cnt, 1u);
        if (arr == (unsigned)(NBLK - 1)) {
            atomicExch(&g_cnt, 0u);
            __threadfence();
            atomicExch(&g_gen, gen + 1u);
        } else {
            while (*((volatile unsigned*)&g_gen) == gen) { }
            __threadfence();
        }
    }
    __syncthreads();
    gen += 1u;
}

// ---------------- embedding gather + best reset ----------------
__global__ void k_embed(const int* __restrict__ src, const int* __restrict__ dst,
                        const float* __restrict__ wte,
                        float* __restrict__ src_e, float* __restrict__ dst_e) {
    size_t i = (size_t)blockIdx.x * blockDim.x + threadIdx.x;
    if (i < 1024) g_best[i] = 0ull;
    const size_t n1 = (size_t)BATCH * SLEN * DIM;
    if (i < n1) {
        int row = (int)(i / DIM), k = (int)(i % DIM);
        src_e[i] = wte[(size_t)src[row] * DIM + k];
    } else {
        size_t ii = i - n1;
        if (ii < (size_t)BATCH * TLEN * DIM) {
            int row = (int)(ii / DIM), k = (int)(ii % DIM);
            dst_e[ii] = wte[(size_t)dst[row] * DIM + k];
        }
    }
}

// ---------------- NT sgemm, packed f32x2, zero-pack mainloop ----------------
// C[m,n] = sum_k A[m,k]*B[n,k] + bias[n] (+resid). 128x128x16 tile,
// 8x8 per thread (4 m-pairs x 8 n), 256 threads. M % 128 == 0.
// Grid: (M/128, ceil(N/128)) -- m on blockIdx.x so co-resident blocks share B.
// AM=true: fused row-argmax via atomicMax into g_best (C not written).
template <bool AM>
__global__ __launch_bounds__(256, 2) void k_sgemm_nt(
    const float* __restrict__ A, const float* __restrict__ B,
    const float* __restrict__ bias, float* __restrict__ C,
    const float* __restrict__ resid, int M, int N, int K)
{
    __shared__ float As[16][132];       // k-major, consecutive m
    __shared__ float Bs2[16][324];      // duplicated (b,b) pairs, skewed
    int tid = threadIdx.x;
    int tx = tid & 15, ty = tid >> 4;
    int m0 = blockIdx.x * 128, n0 = blockIdx.y * 128;
    int lrow = tid >> 2;
    int lcol = (tid & 3) << 2;
    int r0 = lrow, r1 = lrow + 64;

    u64 acc2[4][8];
#pragma unroll
    for (int p = 0; p < 4; ++p)
#pragma unroll
        for (int j = 0; j < 8; ++j) acc2[p][j] = 0ull;

    const float* Ap0 = A + (size_t)(m0 + r0) * K + lcol;
    const float* Ap1 = A + (size_t)(m0 + r1) * K + lcol;
    bool bv0 = (n0 + r0) < N, bv1 = (n0 + r1) < N;
    const float* Bp0 = B + (size_t)(n0 + r0) * K + lcol;
    const float* Bp1 = B + (size_t)(n0 + r1) * K + lcol;

    const float4 z4 = make_float4(0.f, 0.f, 0.f, 0.f);
    float4 pa0 = *(const float4*)(Ap0);
    float4 pa1 = *(const float4*)(Ap1);
    float4 pb0 = bv0 ? *(const float4*)(Bp0) : z4;
    float4 pb1 = bv1 ? *(const float4*)(Bp1) : z4;

    int ob0 = boff(r0), ob1 = boff(r1);

    for (int kt = 0; kt < K; kt += 16) {
        As[lcol + 0][r0] = pa0.x; As[lcol + 1][r0] = pa0.y;
        As[lcol + 2][r0] = pa0.z; As[lcol + 3][r0] = pa0.w;
        As[lcol + 0][r1] = pa1.x; As[lcol + 1][r1] = pa1.y;
        As[lcol + 2][r1] = pa1.z; As[lcol + 3][r1] = pa1.w;
        *(u64*)&Bs2[lcol + 0][ob0] = packf2(pb0.x, pb0.x);
        *(u64*)&Bs2[lcol + 1][ob0] = packf2(pb0.y, pb0.y);
        *(u64*)&Bs2[lcol + 2][ob0] = packf2(pb0.z, pb0.z);
        *(u64*)&Bs2[lcol + 3][ob0] = packf2(pb0.w, pb0.w);
        *(u64*)&Bs2[lcol + 0][ob1] = packf2(pb1.x, pb1.x);
        *(u64*)&Bs2[lcol + 1][ob1] = packf2(pb1.y, pb1.y);
        *(u64*)&Bs2[lcol + 2][ob1] = packf2(pb1.z, pb1.z);
        *(u64*)&Bs2[lcol + 3][ob1] = packf2(pb1.w, pb1.w);
        __syncthreads();

        if (kt + 16 < K) {   // prefetch next k-tile during compute
            pa0 = *(const float4*)(Ap0 + kt + 16);
            pa1 = *(const float4*)(Ap1 + kt + 16);
            pb0 = bv0 ? *(const float4*)(Bp0 + kt + 16) : z4;
            pb1 = bv1 ? *(const float4*)(Bp1 + kt + 16) : z4;
        }

        int bl = 10 * tx;        // low-group base word (boff(tx*4))
        int bh = 160 + 10 * tx;  // high-group base word (boff(64+tx*4))
#pragma unroll
        for (int kk = 0; kk < 16; ++kk) {
            ulonglong2 a01 = *(const ulonglong2*)&As[kk][ty * 4];
            ulonglong2 a23 = *(const ulonglong2*)&As[kk][64 + ty * 4];
            u64 ap[4];
            ap[0] = a01.x; ap[1] = a01.y; ap[2] = a23.x; ap[3] = a23.y;
            const float* brow = &Bs2[kk][0];
            u64 bd[8];
            bd[0] = *(const u64*)(brow + bl + 0);
            bd[1] = *(const u64*)(brow + bl + 2);
            bd[2] = *(const u64*)(brow + bl + 4);
            bd[3] = *(const u64*)(brow + bl + 6);
            bd[4] = *(const u64*)(brow + bh + 0);
            bd[5] = *(const u64*)(brow + bh + 2);
            bd[6] = *(const u64*)(brow + bh + 4);
            bd[7] = *(const u64*)(brow + bh + 6);
#pragma unroll
            for (int p = 0; p < 4; ++p)
#pragma unroll
                for (int j = 0; j < 8; ++j)
                    fma2(acc2[p][j], ap[p], bd[j]);
        }
        __syncthreads();
    }

    if (!AM) {
#pragma unroll
        for (int p = 0; p < 4; ++p) {
            int i0 = (p < 2) ? (ty * 4 + 2 * p) : (64 + ty * 4 + 2 * p - 4);
            size_t mA = (size_t)(m0 + i0);
            size_t mB = mA + 1;
#pragma unroll
            for (int j = 0; j < 8; ++j) {
                int n = n0 + ((j < 4) ? tx * 4 + j : 64 + tx * 4 + j - 4);
                if (n < N) {
                    float lo, hi; unpackf2(acc2[p][j], lo, hi);
                    float bnv = bias[n];
                    float va = lo + bnv, vb = hi + bnv;
                    if (resid) {
                        va += resid[mA * (size_t)N + n];
                        vb += resid[mB * (size_t)N + n];
                    }
                    C[mA * (size_t)N + n] = va;
                    C[mB * (size_t)N + n] = vb;
                }
            }
        }
    } else {
        __shared__ unsigned long long red[128][17];
#pragma unroll
        for (int p = 0; p < 4; ++p) {
            int i0 = (p < 2) ? (ty * 4 + 2 * p) : (64 + ty * 4 + 2 * p - 4);
            unsigned long long lb0 = 0ull, lb1 = 0ull;
#pragma unroll
            for (int j = 0; j < 8; ++j) {
                int n = n0 + ((j < 4) ? tx * 4 + j : 64 + tx * 4 + j - 4);
                if (n < N) {
                    float lo, hi; unpackf2(acc2[p][j], lo, hi);
                    float bnv = bias[n];
                    {
                        unsigned u = __float_as_uint(lo + bnv);
                        unsigned key = (u & 0x80000000u) ? ~u : (u | 0x80000000u);
                        unsigned long long pk = ((unsigned long long)key << 32) |
                            (unsigned long long)(0xFFFFFFFFu - (unsigned)n);
                        if (pk > lb0) lb0 = pk;
                    }
                    {
                        unsigned u = __float_as_uint(hi + bnv);
                        unsigned key = (u & 0x80000000u) ? ~u : (u | 0x80000000u);
                        unsigned long long pk = ((unsigned long long)key << 32) |
                            (unsigned long long)(0xFFFFFFFFu - (unsigned)n);
                        if (pk > lb1) lb1 = pk;
                    }
                }
            }
            red[i0][tx] = lb0;
            red[i0 + 1][tx] = lb1;
        }
        __syncthreads();
        if (tid < 128) {
            unsigned long long bb = 0ull;
#pragma unroll
            for (int x = 0; x < 16; ++x) {
                unsigned long long v = red[tid][x];
                if (v > bb) bb = v;
            }
            atomicMax(&g_best[m0 + tid], bb);
        }
    }
}

// ---------------- persistent GRU scan (input gates precomputed in gi) ----------------
__global__ __launch_bounds__(256) void k_gru_scan_p(
    const float* __restrict__ gi, const float* __restrict__ w_hh,
    const float* __restrict__ b_hh, const int* __restrict__ lens,
    const float* __restrict__ h0, float* __restrict__ out_seq,
    float* __restrict__ h_final, int T)
{
    int w = threadIdx.x >> 5, lane = threadIdx.x & 31;
    int j = blockIdx.x * 8 + w;
    unsigned gen = *((volatile unsigned*)&g_gen);

    if (lane < 8)
        g_h[0][lane * DIM + j] = h0 ? h0[lane * DIM + j] : 0.f;
    gbar(gen);

    const float* wr = w_hh + (size_t)j * DIM;
    const float* wz = w_hh + (size_t)(DIM + j) * DIM;
    const float* wn = w_hh + (size_t)(2 * DIM + j) * DIM;
    float bhr = b_hh[j], bhz = b_hh[DIM + j], bhn = b_hh[2 * DIM + j];
    int mylen = lens[lane & 7];

    for (int t = 0; t < T; ++t) {
        const float* hin = g_h[t & 1];
        float ar[8], az[8], an[8];
#pragma unroll
        for (int b = 0; b < 8; ++b) { ar[b] = 0.f; az[b] = 0.f; an[b] = 0.f; }
        for (int k = lane; k < DIM; k += 32) {
            float w0 = wr[k], w1 = wz[k], w2 = wn[k];
#pragma unroll
            for (int b = 0; b < 8; ++b) {
                float hv = hin[b * DIM + k];
                ar[b] = fmaf(w0, hv, ar[b]);
                az[b] = fmaf(w1, hv, az[b]);
                an[b] = fmaf(w2, hv, an[b]);
            }
        }
#pragma unroll
        for (int b = 0; b < 8; ++b) {
#pragma unroll
            for (int o = 16; o; o >>= 1) {
                ar[b] += __shfl_xor_sync(0xFFFFFFFFu, ar[b], o);
                az[b] += __shfl_xor_sync(0xFFFFFFFFu, az[b], o);
                an[b] += __shfl_xor_sync(0xFFFFFFFFu, an[b], o);
            }
        }
        if (lane < 8) {
            int b = lane;
            const float* gib = gi + (size_t)(b * T + t) * D3;
            float hold = hin[b * DIM + j];
            float r = sigm(gib[j] + ar[b] + bhr);
            float z = sigm(gib[DIM + j] + az[b] + bhz);
            float n = tanhf(gib[2 * DIM + j] + r * (an[b] + bhn));
            float hn = (1.f - z) * n + z * hold;
            bool valid = (t < mylen);
            g_h[(t + 1) & 1][b * DIM + j] = valid ? hn : hold;
            if (out_seq) out_seq[(size_t)(b * T + t) * DIM + j] = valid ? hn : 0.f;
        }
        gbar(gen);
    }
    if (h_final && lane < 8)
        h_final[lane * DIM + j] = g_h[T & 1][lane * DIM + j];
}

// ---------------- persistent scheduled-sampling decode ----------------
__global__ __launch_bounds__(256) void k_decode_p(
    const float* __restrict__ dst_e, const float* __restrict__ wte,
    const float* __restrict__ w_ih, const float* __restrict__ w_hh,
    const float* __restrict__ b_ih, const float* __restrict__ b_hh,
    const float* __restrict__ gumbel, float* __restrict__ fout)
{
    __shared__ int s_orac[8];
    int w = threadIdx.x >> 5, lane = threadIdx.x & 31;
    int j = blockIdx.x * 8 + w;
    unsigned gen = *((volatile unsigned*)&g_gen);

    const float* wir = w_ih + (size_t)j * DIM;
    const float* wiz = w_ih + (size_t)(DIM + j) * DIM;
    const float* win = w_ih + (size_t)(2 * DIM + j) * DIM;
    const float* whr = w_hh + (size_t)j * DIM;
    const float* whz = w_hh + (size_t)(DIM + j) * DIM;
    const float* whn = w_hh + (size_t)(2 * DIM + j) * DIM;
    float bir = b_ih[j], biz = b_ih[DIM + j], bin_ = b_ih[2 * DIM + j];
    float bhr = b_hh[j], bhz = b_hh[DIM + j], bhn = b_hh[2 * DIM + j];

    for (int t = 0; t <= TLEN - 1; ++t) {
        const float* hin = (t == 0) ? g_henc : g_h[(t + 1) & 1];

        const float* xp[8];
        if (t == 0) {
#pragma unroll
            for (int b = 0; b < 8; ++b)
                xp[b] = dst_e + (size_t)b * TLEN * DIM;    // dst_e[:,0,:]
        } else {
            {
                const float* gp = gumbel + ((size_t)(t - 1) * BATCH + w) * DIM;
                const float* hp = hin + w * DIM;
                float bv = -INFINITY; int bi = 0x7FFFFFFF;
                for (int i = lane; i < DIM; i += 32) {
                    float v = hp[i] + gp[i];
                    if (v > bv || (v == bv && i < bi)) { bv = v; bi = i; }
                }
#pragma unroll
                for (int o = 16; o; o >>= 1) {
                    float ov = __shfl_xor_sync(0xFFFFFFFFu, bv, o);
                    int   oi = __shfl_xor_sync(0xFFFFFFFFu, bi, o);
                    if (ov > bv || (ov == bv && oi < bi)) { bv = ov; bi = oi; }
                }
                if (lane == 0) s_orac[w] = bi;
            }
            __syncthreads();
#pragma unroll
            for (int b = 0; b < 8; ++b)
                xp[b] = wte + (size_t)s_orac[b] * DIM;
        }

        float ir[8], iz[8], inn[8], hr[8], hz[8], hn[8];
#pragma unroll
        for (int b = 0; b < 8; ++b) { ir[b]=iz[b]=inn[b]=hr[b]=hz[b]=hn[b]=0.f; }
        for (int k = lane; k < DIM; k += 32) {
            float a0 = wir[k], a1 = wiz[k], a2 = win[k];
            float c0 = whr[k], c1 = whz[k], c2 = whn[k];
#pragma unroll
            for (int b = 0; b < 8; ++b) {
                float xv = xp[b][k];
                float hv = hin[b * DIM + k];
                ir[b]  = fmaf(a0, xv, ir[b]);
                iz[b]  = fmaf(a1, xv, iz[b]);
                inn[b] = fmaf(a2, xv, inn[b]);
                hr[b]  = fmaf(c0, hv, hr[b]);
                hz[b]  = fmaf(c1, hv, hz[b]);
                hn[b]  = fmaf(c2, hv, hn[b]);
            }
        }
#pragma unroll
        for (int b = 0; b < 8; ++b) {
#pragma unroll
            for (int o = 16; o; o >>= 1) {
                ir[b]  += __shfl_xor_sync(0xFFFFFFFFu, ir[b], o);
                iz[b]  += __shfl_xor_sync(0xFFFFFFFFu, iz[b], o);
                inn[b] += __shfl_xor_sync(0xFFFFFFFFu, inn[b], o);
                hr[b]  += __shfl_xor_sync(0xFFFFFFFFu, hr[b], o);
                hz[b]  += __shfl_xor_sync(0xFFFFFFFFu, hz[b], o);
                hn[b]  += __shfl_xor_sync(0xFFFFFFFFu, hn[b], o);
            }
        }
        if (lane < 8) {
            int b = lane;
            float hold = hin[b * DIM + j];
            float r = sigm(ir[b] + bir + hr[b] + bhr);
            float z = sigm(iz[b] + biz + hz[b] + bhz);
            float n = tanhf(inn[b] + bin_ + r * (hn[b] + bhn));
            float hv = (1.f - z) * n + z * hold;
            g_h[t & 1][b * DIM + j] = hv;
            fout[(size_t)(b * TLEN + t) * DIM + j] = hv;
        }
        gbar(gen);
    }
}

// ---------------- misc small kernels ----------------
__global__ void k_gather_cand(const float* __restrict__ wte, float* __restrict__ cand) {
    size_t i = (size_t)blockIdx.x * blockDim.x + threadIdx.x;
    if (i < (size_t)1024 * DIM) {
        int m = (int)(i / DIM), k = (int)(i % DIM);
        unsigned id = 0xFFFFFFFFu - (unsigned)(g_best[m] & 0xFFFFFFFFull);
        cand[i] = wte[(size_t)id * DIM + k];
    }
}

// ---------------- attention: one block per (b,h); thread per query s ----------------
__global__ __launch_bounds__(256) void k_attn(
    const float* __restrict__ q, const float* __restrict__ kk,
    const float* __restrict__ vv, const int* __restrict__ dlen,
    float* __restrict__ ao)
{
    __shared__ float Ks[64][65];
    __shared__ float Vs[64][65];
    int b = blockIdx.x / NHEAD, h = blockIdx.x % NHEAD;
    int s = threadIdx.x;
    int len = dlen[b];

    float qv[HDIM];
    const float* qp = q + ((size_t)(b * SLEN + s)) * DIM + h * HDIM;
#pragma unroll
    for (int d = 0; d < HDIM; ++d) qv[d] = qp[d] * 0.125f;   // 1/sqrt(64)

    float m = -INFINITY, l = 0.f;
    float o[HDIM];
#pragma unroll
    for (int d = 0; d < HDIM; ++d) o[d] = 0.f;

    for (int c = 0; c < 2; ++c) {
        for (int i = threadIdx.x; i < 1024; i += 256) {
            int row = i >> 4, c4 = (i & 15) << 2;
            size_t base = ((size_t)(b * TLEN + c * 64 + row)) * DIM + h * HDIM + c4;
            float4 kvv = *(const float4*)(kk + base);
            float4 vvv = *(const float4*)(vv + base);
            Ks[row][c4 + 0] = kvv.x; Ks[row][c4 + 1] = kvv.y;
            Ks[row][c4 + 2] = kvv.z; Ks[row][c4 + 3] = kvv.w;
            Vs[row][c4 + 0] = vvv.x; Vs[row][c4 + 1] = vvv.y;
            Vs[row][c4 + 2] = vvv.z; Vs[row][c4 + 3] = vvv.w;
        }
        __syncthreads();
        for (int tc = 0; tc < 64; ++tc) {
            int t = c * 64 + tc;
            float sc = 0.f;
#pragma unroll
            for (int d = 0; d < HDIM; ++d) sc = fmaf(qv[d], Ks[tc][d], sc);
            if (t >= len) sc = -1e9f;
            float mn = fmaxf(m, sc);
            float scale = expf(m - mn);       // exp(-inf)=0 on first iteration
            float p = expf(sc - mn);
            l = l * scale + p;
#pragma unroll
            for (int d = 0; d < HDIM; ++d)
                o[d] = o[d] * scale + p * Vs[tc][d];
            m = mn;
        }
        __syncthreads();
    }
    float inv = 1.f / l;
    float* op = ao + ((size_t)(b * SLEN + s)) * DIM + h * HDIM;
#pragma unroll
    for (int d = 0; d < HDIM; ++d) op[d] = o[d] * inv;
}

// ---------------- latent loss (deterministic, fixed partition) ----------------
__global__ void k_loss_part(const float* __restrict__ a, const float* __restrict__ b) {
    __shared__ double red[256];
    int blk = blockIdx.x, tid = threadIdx.x;
    size_t base = (size_t)blk * 3072;
    double s = 0.0;
    for (int i = tid; i < 3072; i += 256) {
        double d = (double)a[base + i] - (double)b[base + i];
        s += d * d;
    }
    red[tid] = s;
    __syncthreads();
    for (int o = 128; o; o >>= 1) {
        if (tid < o) red[tid] += red[tid + o];
        __syncthreads();
    }
    if (tid == 0) g_part[blk] = red[0];
}
__global__ void k_loss_final(float* __restrict__ out) {
    if (threadIdx.x == 0) {
        double s = 0.0;
        for (int i = 0; i < 512; ++i) s += g_part[i];
        out[(size_t)1024 * VOC] = (float)s;
    }
}

// ---------------- host driver ----------------
extern "C" void kernel_launch(void* const* d_in, const int* in_sizes, int n_in,
                              void* d_out, int out_size) {
    const int*   src      = (const int*)d_in[0];
    const int*   src_len  = (const int*)d_in[1];
    const int*   dst      = (const int*)d_in[2];
    const int*   dst_len  = (const int*)d_in[3];
    const float* wte      = (const float*)d_in[4];
    const float* e_wih    = (const float*)d_in[5];
    const float* e_whh    = (const float*)d_in[6];
    const float* e_bih    = (const float*)d_in[7];
    const float* e_bhh    = (const float*)d_in[8];
    const float* d_wih    = (const float*)d_in[9];
    const float* d_whh    = (const float*)d_in[10];
    const float* d_bih    = (const float*)d_in[11];
    const float* d_bhh    = (const float*)d_in[12];
    const float* out_w    = (const float*)d_in[13];
    const float* out_b    = (const float*)d_in[14];
    const float* ll_w     = (const float*)d_in[15];
    const float* ll_b     = (const float*)d_in[16];
    const float* a_inw    = (const float*)d_in[17];
    const float* a_inb    = (const float*)d_in[18];
    const float* a_ow     = (const float*)d_in[19];
    const float* a_ob     = (const float*)d_in[20];
    const float* gumbel   = (const float*)d_in[21];
    float* y = (float*)d_out;

    float* gb = nullptr;    cudaGetSymbolAddress((void**)&gb, g_buf);
    float* hbuf0 = nullptr; cudaGetSymbolAddress((void**)&hbuf0, g_h);
    float* henc = nullptr;  cudaGetSymbolAddress((void**)&henc, g_henc);

    float* src_e  = gb + OFF_SRC_E;
    float* dst_e  = gb + OFF_DST_E;
    float* gi     = gb + OFF_GI;
    float* finalo = gb + OFF_FINAL;
    float* cand   = gb + OFF_CAND;
    float* qb     = gb + OFF_Q;
    float* kb     = gb + OFF_KP;
    float* vb     = gb + OFF_VP;
    float* aob    = gb + OFF_AO;
    float* coutb  = gb + OFF_COUT;
    float* caftb  = gb + OFF_CAFT;
    float* dstout = gb + OFF_DSTOUT;

    // 1) embeddings + best reset
    k_embed<<<9216, 256>>>(src, dst, wte, src_e, dst_e);

    // 2) encoder scan 1 (persistent); h_enc -> g_henc
    k_sgemm_nt<false><<<dim3(16, 18), 256>>>(src_e, e_wih, e_bih, gi, nullptr, 2048, D3, DIM);
    k_gru_scan_p<<<NBLK, 256>>>(gi, e_whh, e_bhh, src_len, nullptr, nullptr, henc, SLEN);

    // 3) scheduled-sampling decode (persistent) -> finalo
    k_decode_p<<<NBLK, 256>>>(dst_e, wte, d_wih, d_whh, d_bih, d_bhh, gumbel, finalo);

    // 4) cand logits + fused argmax; gather cand embeddings
    k_sgemm_nt<true><<<dim3(8, 393), 256>>>(finalo, out_w, out_b, nullptr, nullptr, 1024, VOC, DIM);
    k_gather_cand<<<3072, 256>>>(wte, cand);

    // 5) attention
    k_sgemm_nt<false><<<dim3(16, 6), 256>>>(src_e, a_inw,              a_inb,        qb, nullptr, 2048, DIM, DIM);
    k_sgemm_nt<false><<<dim3(8, 6),  256>>>(cand,  a_inw + 768 * 768,  a_inb + 768,  kb, nullptr, 1024, DIM, DIM);
    k_sgemm_nt<false><<<dim3(8, 6),  256>>>(cand,  a_inw + 1536 * 768, a_inb + 1536, vb, nullptr, 1024, DIM, DIM);
    k_attn<<<96, 256>>>(qb, kb, vb, dst_len, aob);
    k_sgemm_nt<false><<<dim3(16, 6), 256>>>(aob, a_ow, a_ob, coutb, src_e, 2048, DIM, DIM);

    // 6) c_aft + latent loss (c_multi == c_output since PARAM1=0, PARAM2=1)
    k_sgemm_nt<false><<<dim3(16, 6), 256>>>(src_e, ll_w, ll_b, caftb, nullptr, 2048, DIM, DIM);
    k_loss_part<<<512, 256>>>(caftb, coutb);
    k_loss_final<<<1, 32>>>(y);

    // 7) encoder scan 2 on c_output (persistent); final hidden left in g_h[0]
    k_sgemm_nt<false><<<dim3(16, 18), 256>>>(coutb, e_wih, e_bih, gi, nullptr, 2048, D3, DIM);
    k_gru_scan_p<<<NBLK, 256>>>(gi, e_whh, e_bhh, src_len, nullptr, nullptr, nullptr, SLEN);

    // 8) decoder scan (persistent), h0 = g_h[0] (identity re-init), out zero-padded
    k_sgemm_nt<false><<<dim3(8, 18), 256>>>(dst_e, d_wih, d_bih, gi, nullptr, 1024, D3, DIM);
    k_gru_scan_p<<<NBLK, 256>>>(gi, d_whh, d_bhh, dst_len, hbuf0, dstout, nullptr, TLEN);

    // 9) y = dst_out @ out_w^T + out_b
    k_sgemm_nt<false><<<dim3(8, 393), 256>>>(dstout, out_w, out_b, y, nullptr, 1024, VOC, DIM);
}

// round 13
// speedup vs baseline: 1.1650x; 1.1650x over previous
#include <cuda_runtime.h>
#include <cuda_bf16.h>
#include <math.h>

#define DIM   768
#define D3    2304
#define BATCH 8
#define SLEN  256
#define TLEN  128
#define VOC   50257
#define NHEAD 12
#define HDIM  64
#define NBLK  96

typedef unsigned long long u64;
typedef unsigned int u32;

// ---------------- scratch (device globals; no allocation) ----------------
__device__ float g_buf[17301504];          // ~66 MB fp32 scratch
__device__ float g_h[2][BATCH * DIM];
__device__ float g_henc[BATCH * DIM];
__device__ unsigned long long g_best[1024];
__device__ double g_part[512];
__device__ unsigned g_cnt = 0;
__device__ unsigned g_gen = 0;

// bf16 split buffers (hi/lo)
__device__ __nv_bfloat16 g_woh[38597376], g_wol[38597376];   // out_w
__device__ __nv_bfloat16 g_eih[1769472],  g_eil[1769472];    // enc w_ih
__device__ __nv_bfloat16 g_dih[1769472],  g_dil[1769472];    // dec w_ih
__device__ __nv_bfloat16 g_aih[1769472],  g_ail[1769472];    // attn in_w
__device__ __nv_bfloat16 g_aoh[589824],   g_aol[589824];     // attn out_w
__device__ __nv_bfloat16 g_llh[589824],   g_lll[589824];     // ll_w
__device__ __nv_bfloat16 g_sph[7864320],  g_spl[7864320];    // activations

// g_buf offsets (floats)
#define OFF_SRC_E  0u
#define OFF_DST_E  1572864u
#define OFF_GI     2359296u
#define OFF_FINAL  7077888u
#define OFF_CAND   7864320u
#define OFF_Q      8650752u
#define OFF_KP     10223616u
#define OFF_VP     11010048u
#define OFF_AO     11796480u
#define OFF_COUT   13369344u
#define OFF_CAFT   14942208u
#define OFF_DSTOUT 16515072u

// split-activation offsets (elements) in g_sph/g_spl
#define SP_SRCE   0u         // 2048x768
#define SP_FINAL  1572864u   // 1024x768
#define SP_CAND   2359296u   // 1024x768
#define SP_AOB    3145728u   // 2048x768
#define SP_COUT   4718592u   // 2048x768
#define SP_DSTE   6291456u   // 1024x768
#define SP_DSTO   7077888u   // 1024x768

__device__ __forceinline__ float sigm(float x) { return 1.0f / (1.0f + expf(-x)); }

__device__ __forceinline__ u32 smem_u32(const void* p) {
    u32 a;
    asm("{ .reg .u64 t; cvta.to.shared.u64 t, %1; cvt.u32.u64 %0, t; }"
        : "=r"(a) : "l"(p));
    return a;
}

// ---------------- warp-mma helpers (portable PTX, sm_80+) ----------------
__device__ __forceinline__ void ldm4(u32* r, u32 addr) {
    asm volatile("ldmatrix.sync.aligned.m8n8.x4.shared.b16 {%0,%1,%2,%3}, [%4];"
        : "=r"(r[0]), "=r"(r[1]), "=r"(r[2]), "=r"(r[3]) : "r"(addr));
}
__device__ __forceinline__ void mma_bf16(float* d, const u32* a, u32 b0, u32 b1) {
    asm volatile(
        "mma.sync.aligned.m16n8k16.row.col.f32.bf16.bf16.f32 "
        "{%0,%1,%2,%3}, {%4,%5,%6,%7}, {%8,%9}, {%0,%1,%2,%3};"
        : "+f"(d[0]), "+f"(d[1]), "+f"(d[2]), "+f"(d[3])
        : "r"(a[0]), "r"(a[1]), "r"(a[2]), "r"(a[3]), "r"(b0), "r"(b1));
}

// ---------------- grid barrier (persistent scans) ----------------
__device__ __forceinline__ void gbar(unsigned& gen) {
    __syncthreads();
    if (threadIdx.x == 0) {
        __threadfence();
        unsigned arr = atomicAdd(&g_cnt, 1u);
        if (arr == (unsigned)(NBLK - 1)) {
            atomicExch(&g_cnt, 0u);
            __threadfence();
            atomicExch(&g_gen, gen + 1u);
        } else {
            while (*((volatile unsigned*)&g_gen) == gen) { }
            __threadfence();
        }
    }
    __syncthreads();
    gen += 1u;
}

// ---------------- embedding gather + best reset ----------------
__global__ void k_embed(const int* __restrict__ src, const int* __restrict__ dst,
                        const float* __restrict__ wte,
                        float* __restrict__ src_e, float* __restrict__ dst_e) {
    size_t i = (size_t)blockIdx.x * blockDim.x + threadIdx.x;
    if (i < 1024) g_best[i] = 0ull;
    const size_t n1 = (size_t)BATCH * SLEN * DIM;
    if (i < n1) {
        int row = (int)(i / DIM), k = (int)(i % DIM);
        src_e[i] = wte[(size_t)src[row] * DIM + k];
    } else {
        size_t ii = i - n1;
        if (ii < (size_t)BATCH * TLEN * DIM) {
            int row = (int)(ii / DIM), k = (int)(ii % DIM);
            dst_e[ii] = wte[(size_t)dst[row] * DIM + k];
        }
    }
}

// ---------------- fp32 -> (bf16 hi, bf16 lo) split ----------------
__global__ void k_cvt(const float* __restrict__ x, __nv_bfloat16* __restrict__ hi,
                      __nv_bfloat16* __restrict__ lo, int n) {
    int i = blockIdx.x * blockDim.x + threadIdx.x;
    if (i < n) {
        float v = x[i];
        __nv_bfloat16 h = __float2bfloat16(v);
        hi[i] = h;
        lo[i] = __float2bfloat16(v - __bfloat162float(h));
    }
}

// ---------------- bf16-split tensor-core NT GEMM (mma.sync) ----------------
// C[m,n] = sum_k A[m,k]*B[n,k] + bias[n] (+resid).
// A,B as bf16 hi/lo pairs (3-product split). Tile 128x128, K chunk 32.
// 256 threads = 8 warps (4m x 2n), each warp 32m x 64n.
// Grid (M/128, ceil(N/128)); M % 128 == 0.
// AM=true: fused row-argmax into g_best (C not written).
#define KC  32
#define STR 40   // smem row stride in bf16 (16B-aligned, conflict-free)

template <bool AM>
__global__ __launch_bounds__(256) void k_mma(
    const __nv_bfloat16* __restrict__ Ah, const __nv_bfloat16* __restrict__ Al,
    const __nv_bfloat16* __restrict__ Bh, const __nv_bfloat16* __restrict__ Bl,
    const float* __restrict__ bias, float* __restrict__ C,
    const float* __restrict__ resid, int M, int N, int K)
{
    __shared__ __align__(16) __nv_bfloat16 sA[2][128 * STR];
    __shared__ __align__(16) __nv_bfloat16 sB[2][128 * STR];

    int tid = threadIdx.x, wid = tid >> 5, lane = tid & 31;
    int m0 = blockIdx.x * 128, n0 = blockIdx.y * 128;
    int wm = wid & 3, wn = wid >> 2;     // warp tile origin: (wm*32, wn*64)

    float acc[2][8][4];
#pragma unroll
    for (int a = 0; a < 2; ++a)
#pragma unroll
        for (int b = 0; b < 8; ++b)
#pragma unroll
            for (int c = 0; c < 4; ++c) acc[a][b][c] = 0.f;

    u32 aAh = smem_u32(sA[0]), aAl = smem_u32(sA[1]);
    u32 aBh = smem_u32(sB[0]), aBl = smem_u32(sB[1]);

    // ldmatrix lane-address components
    int a_row = wm * 32 + (lane & 7) + ((lane >> 3) & 1) * 8;  // + mf*16
    int a_col = (lane >> 4) * 8;                                // + s*16
    int b_row = wn * 64 + (lane >> 4) * 8 + (lane & 7);         // + p*16
    int b_col = ((lane >> 3) & 1) * 8;                          // + s*16

    const int nchunk = K / KC;
    for (int c = 0; c < nchunk; ++c) {
        int k0 = c * KC;
        for (int i = tid; i < 512; i += 256) {
            int row = i >> 2, seg = i & 3;
            u32 so = (u32)(row * STR + seg * 8);
            size_t asrc = (size_t)(m0 + row) * K + k0 + seg * 8;
            *(uint4*)&sA[0][so] = *(const uint4*)(Ah + asrc);
            *(uint4*)&sA[1][so] = *(const uint4*)(Al + asrc);
            if (n0 + row < N) {
                size_t bsrc = (size_t)(n0 + row) * K + k0 + seg * 8;
                *(uint4*)&sB[0][so] = *(const uint4*)(Bh + bsrc);
                *(uint4*)&sB[1][so] = *(const uint4*)(Bl + bsrc);
            } else {
                uint4 z = make_uint4(0u, 0u, 0u, 0u);
                *(uint4*)&sB[0][so] = z;
                *(uint4*)&sB[1][so] = z;
            }
        }
        __syncthreads();

#pragma unroll
        for (int s = 0; s < 2; ++s) {
            u32 ah[2][4], al[2][4];
#pragma unroll
            for (int mf = 0; mf < 2; ++mf) {
                u32 off = (u32)(((a_row + mf * 16) * STR + s * 16 + a_col) * 2);
                ldm4(ah[mf], aAh + off);
                ldm4(al[mf], aAl + off);
            }
#pragma unroll
            for (int p = 0; p < 4; ++p) {
                u32 off = (u32)(((b_row + p * 16) * STR + s * 16 + b_col) * 2);
                u32 bh[4], bl[4];
                ldm4(bh, aBh + off);
                ldm4(bl, aBl + off);
#pragma unroll
                for (int mf = 0; mf < 2; ++mf) {
#pragma unroll
                    for (int hh = 0; hh < 2; ++hh) {
                        int nf = p * 2 + hh;
                        mma_bf16(acc[mf][nf], ah[mf], bh[hh * 2], bh[hh * 2 + 1]);
                        mma_bf16(acc[mf][nf], ah[mf], bl[hh * 2], bl[hh * 2 + 1]);
                        mma_bf16(acc[mf][nf], al[mf], bh[hh * 2], bh[hh * 2 + 1]);
                    }
                }
            }
        }
        __syncthreads();
    }

    int rbase = m0 + wm * 32 + (lane >> 2);
    int cbase = n0 + wn * 64 + 2 * (lane & 3);

    if (!AM) {
#pragma unroll
        for (int mf = 0; mf < 2; ++mf)
#pragma unroll
            for (int half = 0; half < 2; ++half) {
                size_t row = (size_t)(rbase + mf * 16 + half * 8);
#pragma unroll
                for (int nf = 0; nf < 8; ++nf)
#pragma unroll
                    for (int e = 0; e < 2; ++e) {
                        int col = cbase + nf * 8 + e;
                        if (col < N) {
                            float v = acc[mf][nf][half * 2 + e] + bias[col];
                            if (resid) v += resid[row * (size_t)N + col];
                            C[row * (size_t)N + col] = v;
                        }
                    }
            }
    } else {
#pragma unroll
        for (int mf = 0; mf < 2; ++mf)
#pragma unroll
            for (int half = 0; half < 2; ++half) {
                int row = rbase + mf * 16 + half * 8;
                u64 best = 0ull;
#pragma unroll
                for (int nf = 0; nf < 8; ++nf)
#pragma unroll
                    for (int e = 0; e < 2; ++e) {
                        int col = cbase + nf * 8 + e;
                        if (col < N) {
                            unsigned u = __float_as_uint(acc[mf][nf][half * 2 + e] + bias[col]);
                            unsigned key = (u & 0x80000000u) ? ~u : (u | 0x80000000u);
                            u64 pk = ((u64)key << 32) |
                                     (u64)(0xFFFFFFFFu - (unsigned)col);
                            if (pk > best) best = pk;
                        }
                    }
#pragma unroll
                for (int o = 1; o <= 2; o <<= 1) {
                    u64 ob = __shfl_xor_sync(0xFFFFFFFFu, best, o);
                    if (ob > best) best = ob;
                }
                if ((lane & 3) == 0) atomicMax(&g_best[row], best);
            }
    }
}

// ---------------- persistent GRU scan ----------------
__global__ __launch_bounds__(256) void k_gru_scan_p(
    const float* __restrict__ gi, const float* __restrict__ w_hh,
    const float* __restrict__ b_hh, const int* __restrict__ lens,
    const float* __restrict__ h0, float* __restrict__ out_seq,
    float* __restrict__ h_final, int T)
{
    int w = threadIdx.x >> 5, lane = threadIdx.x & 31;
    int j = blockIdx.x * 8 + w;
    unsigned gen = *((volatile unsigned*)&g_gen);

    if (lane < 8)
        g_h[0][lane * DIM + j] = h0 ? h0[lane * DIM + j] : 0.f;
    gbar(gen);

    const float* wr = w_hh + (size_t)j * DIM;
    const float* wz = w_hh + (size_t)(DIM + j) * DIM;
    const float* wn = w_hh + (size_t)(2 * DIM + j) * DIM;
    float bhr = b_hh[j], bhz = b_hh[DIM + j], bhn = b_hh[2 * DIM + j];
    int mylen = lens[lane & 7];

    for (int t = 0; t < T; ++t) {
        const float* hin = g_h[t & 1];
        float ar[8], az[8], an[8];
#pragma unroll
        for (int b = 0; b < 8; ++b) { ar[b] = 0.f; az[b] = 0.f; an[b] = 0.f; }
        for (int k = lane; k < DIM; k += 32) {
            float w0 = wr[k], w1 = wz[k], w2 = wn[k];
#pragma unroll
            for (int b = 0; b < 8; ++b) {
                float hv = hin[b * DIM + k];
                ar[b] = fmaf(w0, hv, ar[b]);
                az[b] = fmaf(w1, hv, az[b]);
                an[b] = fmaf(w2, hv, an[b]);
            }
        }
#pragma unroll
        for (int b = 0; b < 8; ++b) {
#pragma unroll
            for (int o = 16; o; o >>= 1) {
                ar[b] += __shfl_xor_sync(0xFFFFFFFFu, ar[b], o);
                az[b] += __shfl_xor_sync(0xFFFFFFFFu, az[b], o);
                an[b] += __shfl_xor_sync(0xFFFFFFFFu, an[b], o);
            }
        }
        if (lane < 8) {
            int b = lane;
            const float* gib = gi + (size_t)(b * T + t) * D3;
            float hold = hin[b * DIM + j];
            float r = sigm(gib[j] + ar[b] + bhr);
            float z = sigm(gib[DIM + j] + az[b] + bhz);
            float n = tanhf(gib[2 * DIM + j] + r * (an[b] + bhn));
            float hn = (1.f - z) * n + z * hold;
            bool valid = (t < mylen);
            g_h[(t + 1) & 1][b * DIM + j] = valid ? hn : hold;
            if (out_seq) out_seq[(size_t)(b * T + t) * DIM + j] = valid ? hn : 0.f;
        }
        gbar(gen);
    }
    if (h_final && lane < 8)
        h_final[lane * DIM + j] = g_h[T & 1][lane * DIM + j];
}

// ---------------- persistent scheduled-sampling decode ----------------
__global__ __launch_bounds__(256) void k_decode_p(
    const float* __restrict__ dst_e, const float* __restrict__ wte,
    const float* __restrict__ w_ih, const float* __restrict__ w_hh,
    const float* __restrict__ b_ih, const float* __restrict__ b_hh,
    const float* __restrict__ gumbel, float* __restrict__ fout)
{
    __shared__ int s_orac[8];
    int w = threadIdx.x >> 5, lane = threadIdx.x & 31;
    int j = blockIdx.x * 8 + w;
    unsigned gen = *((volatile unsigned*)&g_gen);

    const float* wir = w_ih + (size_t)j * DIM;
    const float* wiz = w_ih + (size_t)(DIM + j) * DIM;
    const float* win = w_ih + (size_t)(2 * DIM + j) * DIM;
    const float* whr = w_hh + (size_t)j * DIM;
    const float* whz = w_hh + (size_t)(DIM + j) * DIM;
    const float* whn = w_hh + (size_t)(2 * DIM + j) * DIM;
    float bir = b_ih[j], biz = b_ih[DIM + j], bin_ = b_ih[2 * DIM + j];
    float bhr = b_hh[j], bhz = b_hh[DIM + j], bhn = b_hh[2 * DIM + j];

    for (int t = 0; t <= TLEN - 1; ++t) {
        const float* hin = (t == 0) ? g_henc : g_h[(t + 1) & 1];

        const float* xp[8];
        if (t == 0) {
#pragma unroll
            for (int b = 0; b < 8; ++b)
                xp[b] = dst_e + (size_t)b * TLEN * DIM;
        } else {
            {
                const float* gp = gumbel + ((size_t)(t - 1) * BATCH + w) * DIM;
                const float* hp = hin + w * DIM;
                float bv = -INFINITY; int bi = 0x7FFFFFFF;
                for (int i = lane; i < DIM; i += 32) {
                    float v = hp[i] + gp[i];
                    if (v > bv || (v == bv && i < bi)) { bv = v; bi = i; }
                }
#pragma unroll
                for (int o = 16; o; o >>= 1) {
                    float ov = __shfl_xor_sync(0xFFFFFFFFu, bv, o);
                    int   oi = __shfl_xor_sync(0xFFFFFFFFu, bi, o);
                    if (ov > bv || (ov == bv && oi < bi)) { bv = ov; bi = oi; }
                }
                if (lane == 0) s_orac[w] = bi;
            }
            __syncthreads();
#pragma unroll
            for (int b = 0; b < 8; ++b)
                xp[b] = wte + (size_t)s_orac[b] * DIM;
        }

        float ir[8], iz[8], inn[8], hr[8], hz[8], hn[8];
#pragma unroll
        for (int b = 0; b < 8; ++b) { ir[b]=iz[b]=inn[b]=hr[b]=hz[b]=hn[b]=0.f; }
        for (int k = lane; k < DIM; k += 32) {
            float a0 = wir[k], a1 = wiz[k], a2 = win[k];
            float c0 = whr[k], c1 = whz[k], c2 = whn[k];
#pragma unroll
            for (int b = 0; b < 8; ++b) {
                float xv = xp[b][k];
                float hv = hin[b * DIM + k];
                ir[b]  = fmaf(a0, xv, ir[b]);
                iz[b]  = fmaf(a1, xv, iz[b]);
                inn[b] = fmaf(a2, xv, inn[b]);
                hr[b]  = fmaf(c0, hv, hr[b]);
                hz[b]  = fmaf(c1, hv, hz[b]);
                hn[b]  = fmaf(c2, hv, hn[b]);
            }
        }
#pragma unroll
        for (int b = 0; b < 8; ++b) {
#pragma unroll
            for (int o = 16; o; o >>= 1) {
                ir[b]  += __shfl_xor_sync(0xFFFFFFFFu, ir[b], o);
                iz[b]  += __shfl_xor_sync(0xFFFFFFFFu, iz[b], o);
                inn[b] += __shfl_xor_sync(0xFFFFFFFFu, inn[b], o);
                hr[b]  += __shfl_xor_sync(0xFFFFFFFFu, hr[b], o);
                hz[b]  += __shfl_xor_sync(0xFFFFFFFFu, hz[b], o);
                hn[b]  += __shfl_xor_sync(0xFFFFFFFFu, hn[b], o);
            }
        }
        if (lane < 8) {
            int b = lane;
            float hold = hin[b * DIM + j];
            float r = sigm(ir[b] + bir + hr[b] + bhr);
            float z = sigm(iz[b] + biz + hz[b] + bhz);
            float n = tanhf(inn[b] + bin_ + r * (hn[b] + bhn));
            float hv = (1.f - z) * n + z * hold;
            g_h[t & 1][b * DIM + j] = hv;
            fout[(size_t)(b * TLEN + t) * DIM + j] = hv;
        }
        gbar(gen);
    }
}

// ---------------- misc small kernels ----------------
__global__ void k_gather_cand(const float* __restrict__ wte, float* __restrict__ cand) {
    size_t i = (size_t)blockIdx.x * blockDim.x + threadIdx.x;
    if (i < (size_t)1024 * DIM) {
        int m = (int)(i / DIM), k = (int)(i % DIM);
        unsigned id = 0xFFFFFFFFu - (unsigned)(g_best[m] & 0xFFFFFFFFull);
        cand[i] = wte[(size_t)id * DIM + k];
    }
}

// ---------------- attention ----------------
__global__ __launch_bounds__(256) void k_attn(
    const float* __restrict__ q, const float* __restrict__ kk,
    const float* __restrict__ vv, const int* __restrict__ dlen,
    float* __restrict__ ao)
{
    __shared__ float Ks[64][65];
    __shared__ float Vs[64][65];
    int b = blockIdx.x / NHEAD, h = blockIdx.x % NHEAD;
    int s = threadIdx.x;
    int len = dlen[b];

    float qv[HDIM];
    const float* qp = q + ((size_t)(b * SLEN + s)) * DIM + h * HDIM;
#pragma unroll
    for (int d = 0; d < HDIM; ++d) qv[d] = qp[d] * 0.125f;

    float m = -INFINITY, l = 0.f;
    float o[HDIM];
#pragma unroll
    for (int d = 0; d < HDIM; ++d) o[d] = 0.f;

    for (int c = 0; c < 2; ++c) {
        for (int i = threadIdx.x; i < 1024; i += 256) {
            int row = i >> 4, c4 = (i & 15) << 2;
            size_t base = ((size_t)(b * TLEN + c * 64 + row)) * DIM + h * HDIM + c4;
            float4 kvv = *(const float4*)(kk + base);
            float4 vvv = *(const float4*)(vv + base);
            Ks[row][c4 + 0] = kvv.x; Ks[row][c4 + 1] = kvv.y;
            Ks[row][c4 + 2] = kvv.z; Ks[row][c4 + 3] = kvv.w;
            Vs[row][c4 + 0] = vvv.x; Vs[row][c4 + 1] = vvv.y;
            Vs[row][c4 + 2] = vvv.z; Vs[row][c4 + 3] = vvv.w;
        }
        __syncthreads();
        for (int tc = 0; tc < 64; ++tc) {
            int t = c * 64 + tc;
            float sc = 0.f;
#pragma unroll
            for (int d = 0; d < HDIM; ++d) sc = fmaf(qv[d], Ks[tc][d], sc);
            if (t >= len) sc = -1e9f;
            float mn = fmaxf(m, sc);
            float scale = expf(m - mn);
            float p = expf(sc - mn);
            l = l * scale + p;
#pragma unroll
            for (int d = 0; d < HDIM; ++d)
                o[d] = o[d] * scale + p * Vs[tc][d];
            m = mn;
        }
        __syncthreads();
    }
    float inv = 1.f / l;
    float* op = ao + ((size_t)(b * SLEN + s)) * DIM + h * HDIM;
#pragma unroll
    for (int d = 0; d < HDIM; ++d) op[d] = o[d] * inv;
}

// ---------------- latent loss ----------------
__global__ void k_loss_part(const float* __restrict__ a, const float* __restrict__ b) {
    __shared__ double red[256];
    int blk = blockIdx.x, tid = threadIdx.x;
    size_t base = (size_t)blk * 3072;
    double s = 0.0;
    for (int i = tid; i < 3072; i += 256) {
        double d = (double)a[base + i] - (double)b[base + i];
        s += d * d;
    }
    red[tid] = s;
    __syncthreads();
    for (int o = 128; o; o >>= 1) {
        if (tid < o) red[tid] += red[tid + o];
        __syncthreads();
    }
    if (tid == 0) g_part[blk] = red[0];
}
__global__ void k_loss_final(float* __restrict__ out) {
    if (threadIdx.x == 0) {
        double s = 0.0;
        for (int i = 0; i < 512; ++i) s += g_part[i];
        out[(size_t)1024 * VOC] = (float)s;
    }
}

// ---------------- host driver ----------------
extern "C" void kernel_launch(void* const* d_in, const int* in_sizes, int n_in,
                              void* d_out, int out_size) {
    const int*   src      = (const int*)d_in[0];
    const int*   src_len  = (const int*)d_in[1];
    const int*   dst      = (const int*)d_in[2];
    const int*   dst_len  = (const int*)d_in[3];
    const float* wte      = (const float*)d_in[4];
    const float* e_wih    = (const float*)d_in[5];
    const float* e_whh    = (const float*)d_in[6];
    const float* e_bih    = (const float*)d_in[7];
    const float* e_bhh    = (const float*)d_in[8];
    const float* d_wih    = (const float*)d_in[9];
    const float* d_whh    = (const float*)d_in[10];
    const float* d_bih    = (const float*)d_in[11];
    const float* d_bhh    = (const float*)d_in[12];
    const float* out_w    = (const float*)d_in[13];
    const float* out_b    = (const float*)d_in[14];
    const float* ll_w     = (const float*)d_in[15];
    const float* ll_b     = (const float*)d_in[16];
    const float* a_inw    = (const float*)d_in[17];
    const float* a_inb    = (const float*)d_in[18];
    const float* a_ow     = (const float*)d_in[19];
    const float* a_ob     = (const float*)d_in[20];
    const float* gumbel   = (const float*)d_in[21];
    float* y = (float*)d_out;

    float* gb = nullptr;    cudaGetSymbolAddress((void**)&gb, g_buf);
    float* hbuf0 = nullptr; cudaGetSymbolAddress((void**)&hbuf0, g_h);
    float* henc = nullptr;  cudaGetSymbolAddress((void**)&henc, g_henc);
    __nv_bfloat16 *woh, *wol, *eih, *eil, *dih, *dil, *aih, *ail, *aoh, *aol,
                  *llh, *lll, *sph, *spl;
    cudaGetSymbolAddress((void**)&woh, g_woh);
    cudaGetSymbolAddress((void**)&wol, g_wol);
    cudaGetSymbolAddress((void**)&eih, g_eih);
    cudaGetSymbolAddress((void**)&eil, g_eil);
    cudaGetSymbolAddress((void**)&dih, g_dih);
    cudaGetSymbolAddress((void**)&dil, g_dil);
    cudaGetSymbolAddress((void**)&aih, g_aih);
    cudaGetSymbolAddress((void**)&ail, g_ail);
    cudaGetSymbolAddress((void**)&aoh, g_aoh);
    cudaGetSymbolAddress((void**)&aol, g_aol);
    cudaGetSymbolAddress((void**)&llh, g_llh);
    cudaGetSymbolAddress((void**)&lll, g_lll);
    cudaGetSymbolAddress((void**)&sph, g_sph);
    cudaGetSymbolAddress((void**)&spl, g_spl);

    float* src_e  = gb + OFF_SRC_E;
    float* dst_e  = gb + OFF_DST_E;
    float* gi     = gb + OFF_GI;
    float* finalo = gb + OFF_FINAL;
    float* cand   = gb + OFF_CAND;
    float* qb     = gb + OFF_Q;
    float* kb     = gb + OFF_KP;
    float* vb     = gb + OFF_VP;
    float* aob    = gb + OFF_AO;
    float* coutb  = gb + OFF_COUT;
    float* caftb  = gb + OFF_CAFT;
    float* dstout = gb + OFF_DSTOUT;

    // 1) embeddings + weight splits (every launch; no caching allowed)
    k_embed<<<9216, 256>>>(src, dst, wte, src_e, dst_e);
    k_cvt<<<150771, 256>>>(out_w, woh, wol, VOC * DIM);
    k_cvt<<<6912, 256>>>(e_wih, eih, eil, D3 * DIM);
    k_cvt<<<6912, 256>>>(d_wih, dih, dil, D3 * DIM);
    k_cvt<<<6912, 256>>>(a_inw, aih, ail, D3 * DIM);
    k_cvt<<<2304, 256>>>(a_ow, aoh, aol, DIM * DIM);
    k_cvt<<<2304, 256>>>(ll_w, llh, lll, DIM * DIM);

    // 2) encoder scan 1: gi = src_e @ e_wih^T + e_bih, then scan -> g_henc
    k_cvt<<<6144, 256>>>(src_e, sph + SP_SRCE, spl + SP_SRCE, 2048 * DIM);
    k_mma<false><<<dim3(16, 18), 256>>>(sph + SP_SRCE, spl + SP_SRCE, eih, eil,
                                        e_bih, gi, nullptr, 2048, D3, DIM);
    k_gru_scan_p<<<NBLK, 256>>>(gi, e_whh, e_bhh, src_len, nullptr, nullptr, henc, SLEN);

    // 3) scheduled-sampling decode -> finalo
    k_decode_p<<<NBLK, 256>>>(dst_e, wte, d_wih, d_whh, d_bih, d_bhh, gumbel, finalo);

    // 4) cand logits + fused argmax; gather cand embeddings
    k_cvt<<<3072, 256>>>(finalo, sph + SP_FINAL, spl + SP_FINAL, 1024 * DIM);
    k_mma<true><<<dim3(8, 393), 256>>>(sph + SP_FINAL, spl + SP_FINAL, woh, wol,
                                       out_b, nullptr, nullptr, 1024, VOC, DIM);
    k_gather_cand<<<3072, 256>>>(wte, cand);

    // 5) attention: q/k/v projections, attention, out-proj (+residual)
    k_cvt<<<3072, 256>>>(cand, sph + SP_CAND, spl + SP_CAND, 1024 * DIM);
    k_mma<false><<<dim3(16, 6), 256>>>(sph + SP_SRCE, spl + SP_SRCE, aih, ail,
                                       a_inb, qb, nullptr, 2048, DIM, DIM);
    k_mma<false><<<dim3(8, 6), 256>>>(sph + SP_CAND, spl + SP_CAND,
                                      aih + 768 * 768, ail + 768 * 768,
                                      a_inb + 768, kb, nullptr, 1024, DIM, DIM);
    k_mma<false><<<dim3(8, 6), 256>>>(sph + SP_CAND, spl + SP_CAND,
                                      aih + 1536 * 768, ail + 1536 * 768,
                                      a_inb + 1536, vb, nullptr, 1024, DIM, DIM);
    k_attn<<<96, 256>>>(qb, kb, vb, dst_len, aob);
    k_cvt<<<6144, 256>>>(aob, sph + SP_AOB, spl + SP_AOB, 2048 * DIM);
    k_mma<false><<<dim3(16, 6), 256>>>(sph + SP_AOB, spl + SP_AOB, aoh, aol,
                                       a_ob, coutb, src_e, 2048, DIM, DIM);

    // 6) c_aft + latent loss (c_multi == c_output since PARAM1=0, PARAM2=1)
    k_mma<false><<<dim3(16, 6), 256>>>(sph + SP_SRCE, spl + SP_SRCE, llh, lll,
                                       ll_b, caftb, nullptr, 2048, DIM, DIM);
    k_loss_part<<<512, 256>>>(caftb, coutb);
    k_loss_final<<<1, 32>>>(y);

    // 7) encoder scan 2 on c_output
    k_cvt<<<6144, 256>>>(coutb, sph + SP_COUT, spl + SP_COUT, 2048 * DIM);
    k_mma<false><<<dim3(16, 18), 256>>>(sph + SP_COUT, spl + SP_COUT, eih, eil,
                                        e_bih, gi, nullptr, 2048, D3, DIM);
    k_gru_scan_p<<<NBLK, 256>>>(gi, e_whh, e_bhh, src_len, nullptr, nullptr, nullptr, SLEN);

    // 8) decoder scan, h0 = g_h[0]
    k_cvt<<<3072, 256>>>(dst_e, sph + SP_DSTE, spl + SP_DSTE, 1024 * DIM);
    k_mma<false><<<dim3(8, 18), 256>>>(sph + SP_DSTE, spl + SP_DSTE, dih, dil,
                                       d_bih, gi, nullptr, 1024, D3, DIM);
    k_gru_scan_p<<<NBLK, 256>>>(gi, d_whh, d_bhh, dst_len, hbuf0, dstout, nullptr, TLEN);

    // 9) y = dst_out @ out_w^T + out_b
    k_cvt<<<3072, 256>>>(dstout, sph + SP_DSTO, spl + SP_DSTO, 1024 * DIM);
    k_mma<false><<<dim3(8, 393), 256>>>(sph + SP_DSTO, spl + SP_DSTO, woh, wol,
                                        out_b, y, nullptr, 1024, VOC, DIM);
}

// round 15
// speedup vs baseline: 1.9311x; 1.6576x over previous
#include <cuda_runtime.h>
#include <cuda_bf16.h>
#include <math.h>

#define DIM   768
#define D3    2304
#define BATCH 8
#define SLEN  256
#define TLEN  128
#define VOC   50257
#define NHEAD 12
#define HDIM  64
#define NBLK  96

typedef unsigned long long u64;
typedef unsigned int u32;

// ---------------- scratch (device globals; no allocation) ----------------
__device__ __align__(16) float g_buf[17301504];
__device__ __align__(16) float g_h[2][BATCH * DIM];
__device__ __align__(16) float g_henc[BATCH * DIM];
__device__ unsigned long long g_best[1024];
__device__ double g_part[512];
__device__ unsigned g_cnt = 0;
__device__ unsigned g_gen = 0;

// bf16 split buffers (hi/lo)
__device__ __align__(16) __nv_bfloat16 g_woh[38597376], g_wol[38597376];
__device__ __align__(16) __nv_bfloat16 g_eih[1769472],  g_eil[1769472];
__device__ __align__(16) __nv_bfloat16 g_dih[1769472],  g_dil[1769472];
__device__ __align__(16) __nv_bfloat16 g_aih[1769472],  g_ail[1769472];
__device__ __align__(16) __nv_bfloat16 g_aoh[589824],   g_aol[589824];
__device__ __align__(16) __nv_bfloat16 g_llh[589824],   g_lll[589824];
__device__ __align__(16) __nv_bfloat16 g_sph[7864320],  g_spl[7864320];

// g_buf offsets (floats)
#define OFF_SRC_E  0u
#define OFF_DST_E  1572864u
#define OFF_GI     2359296u
#define OFF_FINAL  7077888u
#define OFF_CAND   7864320u
#define OFF_Q      8650752u
#define OFF_KP     10223616u
#define OFF_VP     11010048u
#define OFF_AO     11796480u
#define OFF_COUT   13369344u
#define OFF_CAFT   14942208u
#define OFF_DSTOUT 16515072u

// split-activation offsets (elements) in g_sph/g_spl
#define SP_SRCE   0u
#define SP_FINAL  1572864u
#define SP_CAND   2359296u
#define SP_AOB    3145728u
#define SP_COUT   4718592u
#define SP_DSTE   6291456u
#define SP_DSTO   7077888u

__device__ __forceinline__ float sigm(float x) { return 1.0f / (1.0f + expf(-x)); }

__device__ __forceinline__ u32 smem_u32(const void* p) {
    u32 a;
    asm("{ .reg .u64 t; cvta.to.shared.u64 t, %1; cvt.u32.u64 %0, t; }"
        : "=r"(a) : "l"(p));
    return a;
}

// ---------------- warp-mma + cp.async helpers (portable PTX, sm_80+) ----------------
__device__ __forceinline__ void ldm4(u32* r, u32 addr) {
    asm volatile("ldmatrix.sync.aligned.m8n8.x4.shared.b16 {%0,%1,%2,%3}, [%4];"
        : "=r"(r[0]), "=r"(r[1]), "=r"(r[2]), "=r"(r[3]) : "r"(addr));
}
__device__ __forceinline__ void mma_bf16(float* d, const u32* a, u32 b0, u32 b1) {
    asm volatile(
        "mma.sync.aligned.m16n8k16.row.col.f32.bf16.bf16.f32 "
        "{%0,%1,%2,%3}, {%4,%5,%6,%7}, {%8,%9}, {%0,%1,%2,%3};"
        : "+f"(d[0]), "+f"(d[1]), "+f"(d[2]), "+f"(d[3])
        : "r"(a[0]), "r"(a[1]), "r"(a[2]), "r"(a[3]), "r"(b0), "r"(b1));
}
__device__ __forceinline__ void cpa16(u32 dst, const void* src) {
    asm volatile("cp.async.cg.shared.global [%0], [%1], 16;" :: "r"(dst), "l"(src));
}
#define CPA_COMMIT() asm volatile("cp.async.commit_group;" ::: "memory")
#define CPA_WAIT1()  asm volatile("cp.async.wait_group 1;" ::: "memory")

// ---------------- grid barrier ----------------
__device__ __forceinline__ void gbar(unsigned& gen) {
    __syncthreads();
    if (threadIdx.x == 0) {
        __threadfence();
        unsigned arr = atomicAdd(&g_cnt, 1u);
        if (arr == (unsigned)(NBLK - 1)) {
            atomicExch(&g_cnt, 0u);
            __threadfence();
            atomicExch(&g_gen, gen + 1u);
        } else {
            while (*((volatile unsigned*)&g_gen) == gen) { }
            __threadfence();
        }
    }
    __syncthreads();
    gen += 1u;
}

// ---------------- embedding gather + best reset ----------------
__global__ void k_embed(const int* __restrict__ src, const int* __restrict__ dst,
                        const float* __restrict__ wte,
                        float* __restrict__ src_e, float* __restrict__ dst_e) {
    size_t i = (size_t)blockIdx.x * blockDim.x + threadIdx.x;
    if (i < 1024) g_best[i] = 0ull;
    const size_t n1 = (size_t)BATCH * SLEN * DIM;
    if (i < n1) {
        int row = (int)(i / DIM), k = (int)(i % DIM);
        src_e[i] = wte[(size_t)src[row] * DIM + k];
    } else {
        size_t ii = i - n1;
        if (ii < (size_t)BATCH * TLEN * DIM) {
            int row = (int)(ii / DIM), k = (int)(ii % DIM);
            dst_e[ii] = wte[(size_t)dst[row] * DIM + k];
        }
    }
}

// ---------------- vectorized fp32 -> (bf16 hi, bf16 lo) split ----------------
__global__ void k_cvt4(const float4* __restrict__ x, uint2* __restrict__ hi,
                       uint2* __restrict__ lo, int n4) {
    int i = blockIdx.x * blockDim.x + threadIdx.x;
    if (i < n4) {
        float4 v = x[i];
        __nv_bfloat16 h0 = __float2bfloat16(v.x), h1 = __float2bfloat16(v.y);
        __nv_bfloat16 h2 = __float2bfloat16(v.z), h3 = __float2bfloat16(v.w);
        __nv_bfloat16 l0 = __float2bfloat16(v.x - __bfloat162float(h0));
        __nv_bfloat16 l1 = __float2bfloat16(v.y - __bfloat162float(h1));
        __nv_bfloat16 l2 = __float2bfloat16(v.z - __bfloat162float(h2));
        __nv_bfloat16 l3 = __float2bfloat16(v.w - __bfloat162float(h3));
        uint2 ho, loo;
        ho.x  = (u32)__bfloat16_as_ushort(h0) | ((u32)__bfloat16_as_ushort(h1) << 16);
        ho.y  = (u32)__bfloat16_as_ushort(h2) | ((u32)__bfloat16_as_ushort(h3) << 16);
        loo.x = (u32)__bfloat16_as_ushort(l0) | ((u32)__bfloat16_as_ushort(l1) << 16);
        loo.y = (u32)__bfloat16_as_ushort(l2) | ((u32)__bfloat16_as_ushort(l3) << 16);
        hi[i] = ho;
        lo[i] = loo;
    }
}

// ---------------- bf16-split tensor-core NT GEMM, double-buffered cp.async ----------
// C[m,n] = sum_k A[m,k]*B[n,k] + bias[n] (+resid). Tile 128x128, K chunk 32.
// 256 threads = 8 warps (4m x 2n). Grid (M/128, ceil(N/128)); M % 128 == 0.
// AM=true: fused row-argmax into g_best.
#define KC   32
#define STR  40       // smem row stride in bf16
#define MATB 10240    // bytes per matrix buffer (128*STR*2)
#define BUFB 40960    // bytes per stage (4 matrices)

template <bool AM>
__global__ __launch_bounds__(256) void k_mma(
    const __nv_bfloat16* __restrict__ Ah, const __nv_bfloat16* __restrict__ Al,
    const __nv_bfloat16* __restrict__ Bh, const __nv_bfloat16* __restrict__ Bl,
    const float* __restrict__ bias, float* __restrict__ C,
    const float* __restrict__ resid, int M, int N, int K)
{
    extern __shared__ __align__(16) char dyn[];
    u32 sbase = smem_u32(dyn);

    int tid = threadIdx.x, wid = tid >> 5, lane = tid & 31;
    int m0 = blockIdx.x * 128, n0 = blockIdx.y * 128;
    int wm = wid & 3, wn = wid >> 2;

    float acc[2][8][4];
#pragma unroll
    for (int a = 0; a < 2; ++a)
#pragma unroll
        for (int b = 0; b < 8; ++b)
#pragma unroll
            for (int c = 0; c < 4; ++c) acc[a][b][c] = 0.f;

    int a_row = wm * 32 + (lane & 7) + ((lane >> 3) & 1) * 8;
    int a_col = (lane >> 4) * 8;
    int b_row = wn * 64 + (lane >> 4) * 8 + (lane & 7);
    int b_col = ((lane >> 3) & 1) * 8;

    const int nchunk = K / KC;

    auto ld = [&](int c, int buf) {
        int k0 = c * KC;
        u32 base = sbase + buf * BUFB;
        for (int i = tid; i < 512; i += 256) {
            int row = i >> 2, seg = i & 3;
            u32 so = (u32)(row * STR + seg * 8) * 2;
            size_t ar = (size_t)(m0 + row) * K + k0 + seg * 8;
            cpa16(base + so,            Ah + ar);
            cpa16(base + MATB + so,     Al + ar);
            int brow = n0 + row; if (brow >= N) brow = N - 1;   // clamp; epilogue masks
            size_t br = (size_t)brow * K + k0 + seg * 8;
            cpa16(base + 2 * MATB + so, Bh + br);
            cpa16(base + 3 * MATB + so, Bl + br);
        }
    };

    ld(0, 0);
    CPA_COMMIT();

    for (int c = 0; c < nchunk; ++c) {
        if (c + 1 < nchunk) ld(c + 1, (c + 1) & 1);
        CPA_COMMIT();
        CPA_WAIT1();
        __syncthreads();

        u32 bA_h = sbase + (c & 1) * BUFB;
        u32 bA_l = bA_h + MATB;
        u32 bB_h = bA_h + 2 * MATB;
        u32 bB_l = bA_h + 3 * MATB;

#pragma unroll
        for (int s = 0; s < 2; ++s) {
            u32 ah[2][4], al[2][4];
#pragma unroll
            for (int mf = 0; mf < 2; ++mf) {
                u32 off = (u32)(((a_row + mf * 16) * STR + s * 16 + a_col) * 2);
                ldm4(ah[mf], bA_h + off);
                ldm4(al[mf], bA_l + off);
            }
#pragma unroll
            for (int p = 0; p < 4; ++p) {
                u32 off = (u32)(((b_row + p * 16) * STR + s * 16 + b_col) * 2);
                u32 bh[4], bl[4];
                ldm4(bh, bB_h + off);
                ldm4(bl, bB_l + off);
#pragma unroll
                for (int mf = 0; mf < 2; ++mf) {
#pragma unroll
                    for (int hh = 0; hh < 2; ++hh) {
                        int nf = p * 2 + hh;
                        mma_bf16(acc[mf][nf], ah[mf], bh[hh * 2], bh[hh * 2 + 1]);
                        mma_bf16(acc[mf][nf], ah[mf], bl[hh * 2], bl[hh * 2 + 1]);
                        mma_bf16(acc[mf][nf], al[mf], bh[hh * 2], bh[hh * 2 + 1]);
                    }
                }
            }
        }
        __syncthreads();
    }

    int rbase = m0 + wm * 32 + (lane >> 2);
    int cbase = n0 + wn * 64 + 2 * (lane & 3);

    if (!AM) {
#pragma unroll
        for (int mf = 0; mf < 2; ++mf)
#pragma unroll
            for (int half = 0; half < 2; ++half) {
                size_t row = (size_t)(rbase + mf * 16 + half * 8);
#pragma unroll
                for (int nf = 0; nf < 8; ++nf)
#pragma unroll
                    for (int e = 0; e < 2; ++e) {
                        int col = cbase + nf * 8 + e;
                        if (col < N) {
                            float v = acc[mf][nf][half * 2 + e] + bias[col];
                            if (resid) v += resid[row * (size_t)N + col];
                            C[row * (size_t)N + col] = v;
                        }
                    }
            }
    } else {
#pragma unroll
        for (int mf = 0; mf < 2; ++mf)
#pragma unroll
            for (int half = 0; half < 2; ++half) {
                int row = rbase + mf * 16 + half * 8;
                u64 best = 0ull;
#pragma unroll
                for (int nf = 0; nf < 8; ++nf)
#pragma unroll
                    for (int e = 0; e < 2; ++e) {
                        int col = cbase + nf * 8 + e;
                        if (col < N) {
                            unsigned u = __float_as_uint(acc[mf][nf][half * 2 + e] + bias[col]);
                            unsigned key = (u & 0x80000000u) ? ~u : (u | 0x80000000u);
                            u64 pk = ((u64)key << 32) | (u64)(0xFFFFFFFFu - (unsigned)col);
                            if (pk > best) best = pk;
                        }
                    }
#pragma unroll
                for (int o = 1; o <= 2; o <<= 1) {
                    u64 ob = __shfl_xor_sync(0xFFFFFFFFu, best, o);
                    if (ob > best) best = ob;
                }
                if ((lane & 3) == 0) atomicMax(&g_best[row], best);
            }
    }
}

// ---------------- persistent GRU scan: w_hh in regs, h staged in smem ----------------
__global__ __launch_bounds__(256) void k_gru_scan_p(
    const float* __restrict__ gi, const float* __restrict__ w_hh,
    const float* __restrict__ b_hh, const int* __restrict__ lens,
    const float* __restrict__ h0, float* __restrict__ out_seq,
    float* __restrict__ h_final, int T)
{
    __shared__ __align__(16) float sh[BATCH * DIM];
    int tid = threadIdx.x, w = tid >> 5, lane = tid & 31;
    int j = blockIdx.x * 8 + w;
    unsigned gen = *((volatile unsigned*)&g_gen);

    const float* wr = w_hh + (size_t)j * DIM;
    const float* wz = w_hh + (size_t)(DIM + j) * DIM;
    const float* wn = w_hh + (size_t)(2 * DIM + j) * DIM;
    float wrg[24], wzg[24], wng[24];
#pragma unroll
    for (int i = 0; i < 24; ++i) {
        int k = lane + 32 * i;
        wrg[i] = wr[k]; wzg[i] = wz[k]; wng[i] = wn[k];
    }
    float bhr = b_hh[j], bhz = b_hh[DIM + j], bhn = b_hh[2 * DIM + j];
    int mylen = lens[lane & 7];

    if (lane < 8)
        g_h[0][lane * DIM + j] = h0 ? h0[lane * DIM + j] : 0.f;
    gbar(gen);

    for (int t = 0; t < T; ++t) {
        const float4* hin4 = (const float4*)g_h[t & 1];
        for (int i = tid; i < 1536; i += 256) ((float4*)sh)[i] = hin4[i];
        __syncthreads();

        float ar[8], az[8], an[8];
#pragma unroll
        for (int b = 0; b < 8; ++b) { ar[b] = 0.f; az[b] = 0.f; an[b] = 0.f; }
#pragma unroll
        for (int i = 0; i < 24; ++i) {
            int k = lane + 32 * i;
            float w0 = wrg[i], w1 = wzg[i], w2 = wng[i];
#pragma unroll
            for (int b = 0; b < 8; ++b) {
                float hv = sh[b * DIM + k];
                ar[b] = fmaf(w0, hv, ar[b]);
                az[b] = fmaf(w1, hv, az[b]);
                an[b] = fmaf(w2, hv, an[b]);
            }
        }
#pragma unroll
        for (int b = 0; b < 8; ++b) {
#pragma unroll
            for (int o = 16; o; o >>= 1) {
                ar[b] += __shfl_xor_sync(0xFFFFFFFFu, ar[b], o);
                az[b] += __shfl_xor_sync(0xFFFFFFFFu, az[b], o);
                an[b] += __shfl_xor_sync(0xFFFFFFFFu, an[b], o);
            }
        }
        if (lane < 8) {
            int b = lane;
            const float* gib = gi + (size_t)(b * T + t) * D3;
            float hold = sh[b * DIM + j];
            float r = sigm(gib[j] + ar[b] + bhr);
            float z = sigm(gib[DIM + j] + az[b] + bhz);
            float n = tanhf(gib[2 * DIM + j] + r * (an[b] + bhn));
            float hn = (1.f - z) * n + z * hold;
            bool valid = (t < mylen);
            g_h[(t + 1) & 1][b * DIM + j] = valid ? hn : hold;
            if (out_seq) out_seq[(size_t)(b * T + t) * DIM + j] = valid ? hn : 0.f;
        }
        gbar(gen);
    }
    if (h_final && lane < 8)
        h_final[lane * DIM + j] = g_h[T & 1][lane * DIM + j];
}

// ---------------- persistent decode: w_hh in regs, h staged in smem ----------------
__global__ __launch_bounds__(256) void k_decode_p(
    const float* __restrict__ dst_e, const float* __restrict__ wte,
    const float* __restrict__ w_ih, const float* __restrict__ w_hh,
    const float* __restrict__ b_ih, const float* __restrict__ b_hh,
    const float* __restrict__ gumbel, float* __restrict__ fout)
{
    __shared__ __align__(16) float sh[BATCH * DIM];
    __shared__ int s_orac[8];
    int tid = threadIdx.x, w = tid >> 5, lane = tid & 31;
    int j = blockIdx.x * 8 + w;
    unsigned gen = *((volatile unsigned*)&g_gen);

    const float* wir = w_ih + (size_t)j * DIM;
    const float* wiz = w_ih + (size_t)(DIM + j) * DIM;
    const float* win = w_ih + (size_t)(2 * DIM + j) * DIM;
    const float* whr = w_hh + (size_t)j * DIM;
    const float* whz = w_hh + (size_t)(DIM + j) * DIM;
    const float* whn = w_hh + (size_t)(2 * DIM + j) * DIM;
    float wrg[24], wzg[24], wng[24];
#pragma unroll
    for (int i = 0; i < 24; ++i) {
        int k = lane + 32 * i;
        wrg[i] = whr[k]; wzg[i] = whz[k]; wng[i] = whn[k];
    }
    float bir = b_ih[j], biz = b_ih[DIM + j], bin_ = b_ih[2 * DIM + j];
    float bhr = b_hh[j], bhz = b_hh[DIM + j], bhn = b_hh[2 * DIM + j];

    for (int t = 0; t <= TLEN - 1; ++t) {
        const float* hin = (t == 0) ? g_henc : g_h[(t + 1) & 1];
        const float4* hin4 = (const float4*)hin;
        for (int i = tid; i < 1536; i += 256) ((float4*)sh)[i] = hin4[i];
        __syncthreads();

        const float* xp[8];
        if (t == 0) {
#pragma unroll
            for (int b = 0; b < 8; ++b)
                xp[b] = dst_e + (size_t)b * TLEN * DIM;
        } else {
            {
                const float* gp = gumbel + ((size_t)(t - 1) * BATCH + w) * DIM;
                const float* hp = sh + w * DIM;
                float bv = -INFINITY; int bi = 0x7FFFFFFF;
                for (int i = lane; i < DIM; i += 32) {
                    float v = hp[i] + gp[i];
                    if (v > bv || (v == bv && i < bi)) { bv = v; bi = i; }
                }
#pragma unroll
                for (int o = 16; o; o >>= 1) {
                    float ov = __shfl_xor_sync(0xFFFFFFFFu, bv, o);
                    int   oi = __shfl_xor_sync(0xFFFFFFFFu, bi, o);
                    if (ov > bv || (ov == bv && oi < bi)) { bv = ov; bi = oi; }
                }
                if (lane == 0) s_orac[w] = bi;
            }
            __syncthreads();
#pragma unroll
            for (int b = 0; b < 8; ++b)
                xp[b] = wte + (size_t)s_orac[b] * DIM;
        }

        float ir[8], iz[8], inn[8], hr[8], hz[8], hn[8];
#pragma unroll
        for (int b = 0; b < 8; ++b) { ir[b]=iz[b]=inn[b]=hr[b]=hz[b]=hn[b]=0.f; }
#pragma unroll
        for (int i = 0; i < 24; ++i) {
            int k = lane + 32 * i;
            float a0 = wir[k], a1 = wiz[k], a2 = win[k];
            float c0 = wrg[i], c1 = wzg[i], c2 = wng[i];
#pragma unroll
            for (int b = 0; b < 8; ++b) {
                float xv = xp[b][k];
                float hv = sh[b * DIM + k];
                ir[b]  = fmaf(a0, xv, ir[b]);
                iz[b]  = fmaf(a1, xv, iz[b]);
                inn[b] = fmaf(a2, xv, inn[b]);
                hr[b]  = fmaf(c0, hv, hr[b]);
                hz[b]  = fmaf(c1, hv, hz[b]);
                hn[b]  = fmaf(c2, hv, hn[b]);
            }
        }
#pragma unroll
        for (int b = 0; b < 8; ++b) {
#pragma unroll
            for (int o = 16; o; o >>= 1) {
                ir[b]  += __shfl_xor_sync(0xFFFFFFFFu, ir[b], o);
                iz[b]  += __shfl_xor_sync(0xFFFFFFFFu, iz[b], o);
                inn[b] += __shfl_xor_sync(0xFFFFFFFFu, inn[b], o);
                hr[b]  += __shfl_xor_sync(0xFFFFFFFFu, hr[b], o);
                hz[b]  += __shfl_xor_sync(0xFFFFFFFFu, hz[b], o);
                hn[b]  += __shfl_xor_sync(0xFFFFFFFFu, hn[b], o);
            }
        }
        if (lane < 8) {
            int b = lane;
            float hold = sh[b * DIM + j];
            float r = sigm(ir[b] + bir + hr[b] + bhr);
            float z = sigm(iz[b] + biz + hz[b] + bhz);
            float n = tanhf(inn[b] + bin_ + r * (hn[b] + bhn));
            float hv = (1.f - z) * n + z * hold;
            g_h[t & 1][b * DIM + j] = hv;
            fout[(size_t)(b * TLEN + t) * DIM + j] = hv;
        }
        gbar(gen);
    }
}

// ---------------- misc small kernels ----------------
__global__ void k_gather_cand(const float* __restrict__ wte, float* __restrict__ cand) {
    size_t i = (size_t)blockIdx.x * blockDim.x + threadIdx.x;
    if (i < (size_t)1024 * DIM) {
        int m = (int)(i / DIM), k = (int)(i % DIM);
        unsigned id = 0xFFFFFFFFu - (unsigned)(g_best[m] & 0xFFFFFFFFull);
        cand[i] = wte[(size_t)id * DIM + k];
    }
}

// ---------------- attention ----------------
__global__ __launch_bounds__(256) void k_attn(
    const float* __restrict__ q, const float* __restrict__ kk,
    const float* __restrict__ vv, const int* __restrict__ dlen,
    float* __restrict__ ao)
{
    __shared__ float Ks[64][65];
    __shared__ float Vs[64][65];
    int b = blockIdx.x / NHEAD, h = blockIdx.x % NHEAD;
    int s = threadIdx.x;
    int len = dlen[b];

    float qv[HDIM];
    const float* qp = q + ((size_t)(b * SLEN + s)) * DIM + h * HDIM;
#pragma unroll
    for (int d = 0; d < HDIM; ++d) qv[d] = qp[d] * 0.125f;

    float m = -INFINITY, l = 0.f;
    float o[HDIM];
#pragma unroll
    for (int d = 0; d < HDIM; ++d) o[d] = 0.f;

    for (int c = 0; c < 2; ++c) {
        for (int i = threadIdx.x; i < 1024; i += 256) {
            int row = i >> 4, c4 = (i & 15) << 2;
            size_t base = ((size_t)(b * TLEN + c * 64 + row)) * DIM + h * HDIM + c4;
            float4 kvv = *(const float4*)(kk + base);
            float4 vvv = *(const float4*)(vv + base);
            Ks[row][c4 + 0] = kvv.x; Ks[row][c4 + 1] = kvv.y;
            Ks[row][c4 + 2] = kvv.z; Ks[row][c4 + 3] = kvv.w;
            Vs[row][c4 + 0] = vvv.x; Vs[row][c4 + 1] = vvv.y;
            Vs[row][c4 + 2] = vvv.z; Vs[row][c4 + 3] = vvv.w;
        }
        __syncthreads();
        for (int tc = 0; tc < 64; ++tc) {
            int t = c * 64 + tc;
            float sc = 0.f;
#pragma unroll
            for (int d = 0; d < HDIM; ++d) sc = fmaf(qv[d], Ks[tc][d], sc);
            if (t >= len) sc = -1e9f;
            float mn = fmaxf(m, sc);
            float scale = expf(m - mn);
            float p = expf(sc - mn);
            l = l * scale + p;
#pragma unroll
            for (int d = 0; d < HDIM; ++d)
                o[d] = o[d] * scale + p * Vs[tc][d];
            m = mn;
        }
        __syncthreads();
    }
    float inv = 1.f / l;
    float* op = ao + ((size_t)(b * SLEN + s)) * DIM + h * HDIM;
#pragma unroll
    for (int d = 0; d < HDIM; ++d) op[d] = o[d] * inv;
}

// ---------------- latent loss ----------------
__global__ void k_loss_part(const float* __restrict__ a, const float* __restrict__ b) {
    __shared__ double red[256];
    int blk = blockIdx.x, tid = threadIdx.x;
    size_t base = (size_t)blk * 3072;
    double s = 0.0;
    for (int i = tid; i < 3072; i += 256) {
        double d = (double)a[base + i] - (double)b[base + i];
        s += d * d;
    }
    red[tid] = s;
    __syncthreads();
    for (int o = 128; o; o >>= 1) {
        if (tid < o) red[tid] += red[tid + o];
        __syncthreads();
    }
    if (tid == 0) g_part[blk] = red[0];
}
__global__ void k_loss_final(float* __restrict__ out) {
    if (threadIdx.x == 0) {
        double s = 0.0;
        for (int i = 0; i < 512; ++i) s += g_part[i];
        out[(size_t)1024 * VOC] = (float)s;
    }
}

// ---------------- host driver ----------------
extern "C" void kernel_launch(void* const* d_in, const int* in_sizes, int n_in,
                              void* d_out, int out_size) {
    const int*   src      = (const int*)d_in[0];
    const int*   src_len  = (const int*)d_in[1];
    const int*   dst      = (const int*)d_in[2];
    const int*   dst_len  = (const int*)d_in[3];
    const float* wte      = (const float*)d_in[4];
    const float* e_wih    = (const float*)d_in[5];
    const float* e_whh    = (const float*)d_in[6];
    const float* e_bih    = (const float*)d_in[7];
    const float* e_bhh    = (const float*)d_in[8];
    const float* d_wih    = (const float*)d_in[9];
    const float* d_whh    = (const float*)d_in[10];
    const float* d_bih    = (const float*)d_in[11];
    const float* d_bhh    = (const float*)d_in[12];
    const float* out_w    = (const float*)d_in[13];
    const float* out_b    = (const float*)d_in[14];
    const float* ll_w     = (const float*)d_in[15];
    const float* ll_b     = (const float*)d_in[16];
    const float* a_inw    = (const float*)d_in[17];
    const float* a_inb    = (const float*)d_in[18];
    const float* a_ow     = (const float*)d_in[19];
    const float* a_ob     = (const float*)d_in[20];
    const float* gumbel   = (const float*)d_in[21];
    float* y = (float*)d_out;

    float* gb = nullptr;    cudaGetSymbolAddress((void**)&gb, g_buf);
    float* hbuf0 = nullptr; cudaGetSymbolAddress((void**)&hbuf0, g_h);
    float* henc = nullptr;  cudaGetSymbolAddress((void**)&henc, g_henc);
    __nv_bfloat16 *woh, *wol, *eih, *eil, *dih, *dil, *aih, *ail, *aoh, *aol,
                  *llh, *lll, *sph, *spl;
    cudaGetSymbolAddress((void**)&woh, g_woh);
    cudaGetSymbolAddress((void**)&wol, g_wol);
    cudaGetSymbolAddress((void**)&eih, g_eih);
    cudaGetSymbolAddress((void**)&eil, g_eil);
    cudaGetSymbolAddress((void**)&dih, g_dih);
    cudaGetSymbolAddress((void**)&dil, g_dil);
    cudaGetSymbolAddress((void**)&aih, g_aih);
    cudaGetSymbolAddress((void**)&ail, g_ail);
    cudaGetSymbolAddress((void**)&aoh, g_aoh);
    cudaGetSymbolAddress((void**)&aol, g_aol);
    cudaGetSymbolAddress((void**)&llh, g_llh);
    cudaGetSymbolAddress((void**)&lll, g_lll);
    cudaGetSymbolAddress((void**)&sph, g_sph);
    cudaGetSymbolAddress((void**)&spl, g_spl);

    const int DYN = 2 * BUFB;   // 81920
    cudaFuncSetAttribute(k_mma<false>, cudaFuncAttributeMaxDynamicSharedMemorySize, DYN);
    cudaFuncSetAttribute(k_mma<true>,  cudaFuncAttributeMaxDynamicSharedMemorySize, DYN);

    float* src_e  = gb + OFF_SRC_E;
    float* dst_e  = gb + OFF_DST_E;
    float* gi     = gb + OFF_GI;
    float* finalo = gb + OFF_FINAL;
    float* cand   = gb + OFF_CAND;
    float* qb     = gb + OFF_Q;
    float* kb     = gb + OFF_KP;
    float* vb     = gb + OFF_VP;
    float* aob    = gb + OFF_AO;
    float* coutb  = gb + OFF_COUT;
    float* caftb  = gb + OFF_CAFT;
    float* dstout = gb + OFF_DSTOUT;

    // FIXED: grid covers ceil(n4/256) blocks (R14 bug: (n)/1024 truncated for
    // VOC*DIM, leaving the last out_w row unconverted -> rel_err 4e-3).
    #define CVT4(xx, hh, ll, n) \
        k_cvt4<<<(((n) / 4) + 255) / 256, 256>>>((const float4*)(xx), (uint2*)(hh), (uint2*)(ll), (n) / 4)

    k_embed<<<9216, 256>>>(src, dst, wte, src_e, dst_e);                 // 1
    CVT4(src_e, sph + SP_SRCE, spl + SP_SRCE, 2048 * DIM);               // 2
    CVT4(e_wih, eih, eil, D3 * DIM);                                     // 3
    CVT4(d_wih, dih, dil, D3 * DIM);                                     // 4
    CVT4(a_inw, aih, ail, D3 * DIM);                                     // 5
    k_mma<false><<<dim3(16, 18), 256, DYN>>>(sph + SP_SRCE, spl + SP_SRCE,
                                             eih, eil, e_bih, gi, nullptr,
                                             2048, D3, DIM);             // 6 (profiled)
    k_gru_scan_p<<<NBLK, 256>>>(gi, e_whh, e_bhh, src_len, nullptr, nullptr, henc, SLEN);

    k_decode_p<<<NBLK, 256>>>(dst_e, wte, d_wih, d_whh, d_bih, d_bhh, gumbel, finalo);

    CVT4(out_w, woh, wol, VOC * DIM);
    CVT4(finalo, sph + SP_FINAL, spl + SP_FINAL, 1024 * DIM);
    k_mma<true><<<dim3(8, 393), 256, DYN>>>(sph + SP_FINAL, spl + SP_FINAL, woh, wol,
                                            out_b, nullptr, nullptr, 1024, VOC, DIM);
    k_gather_cand<<<3072, 256>>>(wte, cand);

    CVT4(cand, sph + SP_CAND, spl + SP_CAND, 1024 * DIM);
    k_mma<false><<<dim3(16, 6), 256, DYN>>>(sph + SP_SRCE, spl + SP_SRCE, aih, ail,
                                            a_inb, qb, nullptr, 2048, DIM, DIM);
    k_mma<false><<<dim3(8, 6), 256, DYN>>>(sph + SP_CAND, spl + SP_CAND,
                                           aih + 768 * 768, ail + 768 * 768,
                                           a_inb + 768, kb, nullptr, 1024, DIM, DIM);
    k_mma<false><<<dim3(8, 6), 256, DYN>>>(sph + SP_CAND, spl + SP_CAND,
                                           aih + 1536 * 768, ail + 1536 * 768,
                                           a_inb + 1536, vb, nullptr, 1024, DIM, DIM);
    k_attn<<<96, 256>>>(qb, kb, vb, dst_len, aob);
    CVT4(aob, sph + SP_AOB, spl + SP_AOB, 2048 * DIM);
    CVT4(a_ow, aoh, aol, DIM * DIM);
    k_mma<false><<<dim3(16, 6), 256, DYN>>>(sph + SP_AOB, spl + SP_AOB, aoh, aol,
                                            a_ob, coutb, src_e, 2048, DIM, DIM);

    CVT4(ll_w, llh, lll, DIM * DIM);
    k_mma<false><<<dim3(16, 6), 256, DYN>>>(sph + SP_SRCE, spl + SP_SRCE, llh, lll,
                                            ll_b, caftb, nullptr, 2048, DIM, DIM);
    k_loss_part<<<512, 256>>>(caftb, coutb);
    k_loss_final<<<1, 32>>>(y);

    CVT4(coutb, sph + SP_COUT, spl + SP_COUT, 2048 * DIM);
    k_mma<false><<<dim3(16, 18), 256, DYN>>>(sph + SP_COUT, spl + SP_COUT, eih, eil,
                                             e_bih, gi, nullptr, 2048, D3, DIM);
    k_gru_scan_p<<<NBLK, 256>>>(gi, e_whh, e_bhh, src_len, nullptr, nullptr, nullptr, SLEN);

    CVT4(dst_e, sph + SP_DSTE, spl + SP_DSTE, 1024 * DIM);
    k_mma<false><<<dim3(8, 18), 256, DYN>>>(sph + SP_DSTE, spl + SP_DSTE, dih, dil,
                                            d_bih, gi, nullptr, 1024, D3, DIM);
    k_gru_scan_p<<<NBLK, 256>>>(gi, d_whh, d_bhh, dst_len, hbuf0, dstout, nullptr, TLEN);

    CVT4(dstout, sph + SP_DSTO, spl + SP_DSTO, 1024 * DIM);
    k_mma<false><<<dim3(8, 393), 256, DYN>>>(sph + SP_DSTO, spl + SP_DSTO, woh, wol,
                                             out_b, y, nullptr, 1024, VOC, DIM);
}